// round 2
// baseline (speedup 1.0000x reference)
#include <cuda_runtime.h>
#include <math.h>

#define K_BINS   8
#define TAIL     3.0f
#define MIN_W    0.001f
#define MIN_H    0.001f
#define MIN_D    0.001f

#define NROWS    8192
#define NDIMS    2048
#define NPAR     (K_BINS * 3 - 1)   // 23

#define TILE_D   128
#define THREADS  256
#define ROWS_PB  128                 // rows per block

// shared layout, all fields are [nbins][TILE_D] floats
#define OF_KN  (0 * TILE_D)          // interior knots cw[1..7]      : 7 rows
#define OF_IW  (7 * TILE_D)          // 1/width per bin              : 8 rows
#define OF_CW  (15 * TILE_D)         // cw[bin]                      : 8 rows
#define OF_DL  (23 * TILE_D)         // delta = ih/iw per bin        : 8 rows
#define OF_CH  (31 * TILE_D)         // ch[bin]                      : 8 rows
#define OF_IH  (39 * TILE_D)         // ih per bin                   : 8 rows
#define OF_DV  (47 * TILE_D)         // derivs[0..8]                 : 9 rows
#define SM_FLOATS (56 * TILE_D)      // 7168 floats = 28 KB

__global__ __launch_bounds__(THREADS)
void rqs_kernel(const float* __restrict__ inputs,
                const float* __restrict__ params,
                float* __restrict__ out_base)
{
    __shared__ float sm[SM_FLOATS];

    const int tid  = threadIdx.x;
    const int col0 = blockIdx.x * TILE_D;

    // ---------------- table build: one thread per dim ----------------
    if (tid < TILE_D) {
        const float* p = params + (size_t)(col0 + tid) * NPAR;
        float uw[K_BINS], uh[K_BINS], ud[K_BINS - 1];
        #pragma unroll
        for (int j = 0; j < K_BINS; j++)      uw[j] = p[j];
        #pragma unroll
        for (int j = 0; j < K_BINS; j++)      uh[j] = p[K_BINS + j];
        #pragma unroll
        for (int j = 0; j < K_BINS - 1; j++)  ud[j] = p[2 * K_BINS + j];

        // widths: softmax -> affine -> cumsum -> knots
        float cw[K_BINS + 1], ch[K_BINS + 1];
        {
            float m = uw[0];
            #pragma unroll
            for (int j = 1; j < K_BINS; j++) m = fmaxf(m, uw[j]);
            float e[K_BINS], s = 0.0f;
            #pragma unroll
            for (int j = 0; j < K_BINS; j++) { e[j] = expf(uw[j] - m); s += e[j]; }
            float inv_s = 1.0f / s;
            float acc = 0.0f;
            cw[0] = -TAIL;
            #pragma unroll
            for (int j = 0; j < K_BINS; j++) {
                float wj = fmaf(1.0f - MIN_W * K_BINS, e[j] * inv_s, MIN_W);
                acc += wj;
                cw[j + 1] = fmaf(2.0f * TAIL, acc, -TAIL);
            }
            cw[K_BINS] = TAIL;
        }
        {
            float m = uh[0];
            #pragma unroll
            for (int j = 1; j < K_BINS; j++) m = fmaxf(m, uh[j]);
            float e[K_BINS], s = 0.0f;
            #pragma unroll
            for (int j = 0; j < K_BINS; j++) { e[j] = expf(uh[j] - m); s += e[j]; }
            float inv_s = 1.0f / s;
            float acc = 0.0f;
            ch[0] = -TAIL;
            #pragma unroll
            for (int j = 0; j < K_BINS; j++) {
                float hj = fmaf(1.0f - MIN_H * K_BINS, e[j] * inv_s, MIN_H);
                acc += hj;
                ch[j + 1] = fmaf(2.0f * TAIL, acc, -TAIL);
            }
            ch[K_BINS] = TAIL;
        }
        float dv[K_BINS + 1];
        dv[0] = 1.0f;                  // MIN_D + softplus(log(exp(1-MIN_D)-1)) == 1
        dv[K_BINS] = 1.0f;
        #pragma unroll
        for (int j = 0; j < K_BINS - 1; j++)
            dv[j + 1] = MIN_D + log1pf(expf(ud[j]));

        // store: interior knots
        #pragma unroll
        for (int j = 0; j < 7; j++) sm[OF_KN + j * TILE_D + tid] = cw[j + 1];
        // per-bin fields
        #pragma unroll
        for (int b = 0; b < K_BINS; b++) {
            float iw = cw[b + 1] - cw[b];
            float ih = ch[b + 1] - ch[b];
            sm[OF_IW + b * TILE_D + tid] = 1.0f / iw;
            sm[OF_CW + b * TILE_D + tid] = cw[b];
            sm[OF_DL + b * TILE_D + tid] = ih / iw;
            sm[OF_CH + b * TILE_D + tid] = ch[b];
            sm[OF_IH + b * TILE_D + tid] = ih;
        }
        #pragma unroll
        for (int j = 0; j <= K_BINS; j++) sm[OF_DV + j * TILE_D + tid] = dv[j];
    }
    __syncthreads();

    // ---------------- main elementwise loop ----------------
    const int tx  = tid & (TILE_D - 1);
    const int ty  = tid >> 7;                    // 0 or 1
    const int col = col0 + tx;
    const int row0 = blockIdx.y * ROWS_PB + ty;

    const float* __restrict__ inp = inputs;
    float* __restrict__ o_out = out_base;
    float* __restrict__ o_ld  = out_base + (size_t)NROWS * NDIMS;

    #pragma unroll 4
    for (int i = 0; i < ROWS_PB / 2; i++) {
        const int r = row0 + i * 2;
        const size_t off = (size_t)r * NDIMS + col;
        const float g = inp[off];

        const bool inside = (g >= -TAIL) && (g <= TAIL);
        const float x = fminf(fmaxf(g, -TAIL), TAIL);

        // branchless binary search over interior knots cw[1..7] (kn[0..6])
        int idx = 0;
        if (x >= sm[OF_KN + 3 * TILE_D + tx]) idx = 4;
        if (x >= sm[OF_KN + (idx + 1) * TILE_D + tx]) idx += 2;
        if (x >= sm[OF_KN + idx * TILE_D + tx]) idx += 1;

        const float invw  = sm[OF_IW + idx * TILE_D + tx];
        const float icw   = sm[OF_CW + idx * TILE_D + tx];
        const float delta = sm[OF_DL + idx * TILE_D + tx];
        const float ich   = sm[OF_CH + idx * TILE_D + tx];
        const float ih    = sm[OF_IH + idx * TILE_D + tx];
        const float dlo   = sm[OF_DV + idx * TILE_D + tx];
        const float dhi   = sm[OF_DV + (idx + 1) * TILE_D + tx];

        const float theta = (x - icw) * invw;
        const float omt   = 1.0f - theta;
        const float t1m   = theta * omt;
        const float th2   = theta * theta;

        const float num = ih * fmaf(delta, th2, dlo * t1m);
        const float den = fmaf(fmaf(-2.0f, delta, dlo + dhi), t1m, delta);
        const float rden = __fdividef(1.0f, den);

        const float o  = fmaf(num, rden, ich);
        const float dn = delta * delta *
                         (fmaf(dhi, th2, 2.0f * delta * t1m) + dlo * omt * omt);
        const float l  = __logf(dn * rden * rden);

        o_out[off] = inside ? o : g;
        o_ld[off]  = inside ? l : 0.0f;
    }
}

extern "C" void kernel_launch(void* const* d_in, const int* in_sizes, int n_in,
                              void* d_out, int out_size)
{
    const float* inputs = (const float*)d_in[0];
    const float* params = (const float*)d_in[1];
    float* out = (float*)d_out;

    dim3 grid(NDIMS / TILE_D, NROWS / ROWS_PB);   // (16, 64)
    rqs_kernel<<<grid, THREADS>>>(inputs, params, out);
}

// round 5
// speedup vs baseline: 1.0810x; 1.0810x over previous
#include <cuda_runtime.h>
#include <math.h>

#define K_BINS   8
#define TAIL     3.0f
#define MIN_W    0.001f
#define MIN_H    0.001f
#define MIN_D    0.001f

#define NROWS    8192
#define NDIMS    2048
#define NPAR     (K_BINS * 3 - 1)   // 23

#define TILE_D   128
#define THREADS  256
#define ROWS_PB  128                 // rows per block

// shared layout (floats):
//   knots:  rows 0..6            kn[j][tx] = cw[j+1]   (interior knots)
//   fields: row 7 + f*8 + bin    f in {invw, c, delta, ich, ih, dlo, s}
#define OF_F      (7 * TILE_D)
#define F_STRIDE  (8 * TILE_D)          // 1024 floats = 4096 B between fields
#define SM_FLOATS (7 * TILE_D + 7 * 8 * TILE_D)   // 63 rows = 31.5 KB

__global__ __launch_bounds__(THREADS)
void rqs_kernel(const float* __restrict__ inputs,
                const float* __restrict__ params,
                float* __restrict__ out_base)
{
    __shared__ float sm[SM_FLOATS];

    const int tid  = threadIdx.x;
    const int col0 = blockIdx.x * TILE_D;

    // ---------------- table build: one thread per dim ----------------
    if (tid < TILE_D) {
        const float* p = params + (size_t)(col0 + tid) * NPAR;
        float uw[K_BINS], uh[K_BINS], ud[K_BINS - 1];
        #pragma unroll
        for (int j = 0; j < K_BINS; j++)      uw[j] = p[j];
        #pragma unroll
        for (int j = 0; j < K_BINS; j++)      uh[j] = p[K_BINS + j];
        #pragma unroll
        for (int j = 0; j < K_BINS - 1; j++)  ud[j] = p[2 * K_BINS + j];

        float cw[K_BINS + 1], ch[K_BINS + 1];
        {
            float m = uw[0];
            #pragma unroll
            for (int j = 1; j < K_BINS; j++) m = fmaxf(m, uw[j]);
            float e[K_BINS], ssum = 0.0f;
            #pragma unroll
            for (int j = 0; j < K_BINS; j++) { e[j] = expf(uw[j] - m); ssum += e[j]; }
            float inv_s = 1.0f / ssum;
            float acc = 0.0f;
            cw[0] = -TAIL;
            #pragma unroll
            for (int j = 0; j < K_BINS; j++) {
                float wj = fmaf(1.0f - MIN_W * K_BINS, e[j] * inv_s, MIN_W);
                acc += wj;
                cw[j + 1] = fmaf(2.0f * TAIL, acc, -TAIL);
            }
            cw[K_BINS] = TAIL;
        }
        {
            float m = uh[0];
            #pragma unroll
            for (int j = 1; j < K_BINS; j++) m = fmaxf(m, uh[j]);
            float e[K_BINS], ssum = 0.0f;
            #pragma unroll
            for (int j = 0; j < K_BINS; j++) { e[j] = expf(uh[j] - m); ssum += e[j]; }
            float inv_s = 1.0f / ssum;
            float acc = 0.0f;
            ch[0] = -TAIL;
            #pragma unroll
            for (int j = 0; j < K_BINS; j++) {
                float hj = fmaf(1.0f - MIN_H * K_BINS, e[j] * inv_s, MIN_H);
                acc += hj;
                ch[j + 1] = fmaf(2.0f * TAIL, acc, -TAIL);
            }
            ch[K_BINS] = TAIL;
        }
        float dv[K_BINS + 1];
        dv[0] = 1.0f;                  // MIN_D + softplus(log(exp(1-MIN_D)-1)) == 1
        dv[K_BINS] = 1.0f;
        #pragma unroll
        for (int j = 0; j < K_BINS - 1; j++)
            dv[j + 1] = MIN_D + log1pf(expf(ud[j]));

        // interior knots
        #pragma unroll
        for (int j = 0; j < 7; j++) sm[j * TILE_D + tid] = cw[j + 1];
        // per-bin fields
        #pragma unroll
        for (int b = 0; b < K_BINS; b++) {
            const float iw    = cw[b + 1] - cw[b];
            const float ih    = ch[b + 1] - ch[b];
            const float invw  = 1.0f / iw;
            const float delta = ih * invw;
            const int   o     = OF_F + b * TILE_D + tid;
            sm[o + 0 * F_STRIDE] = invw;
            sm[o + 1 * F_STRIDE] = -cw[b] * invw;                    // c
            sm[o + 2 * F_STRIDE] = delta;
            sm[o + 3 * F_STRIDE] = ch[b];                            // ich
            sm[o + 4 * F_STRIDE] = ih;
            sm[o + 5 * F_STRIDE] = dv[b];                            // dlo
            sm[o + 6 * F_STRIDE] = dv[b] + dv[b + 1] - 2.0f * delta; // s
        }
    }
    __syncthreads();

    // ---------------- main elementwise loop ----------------
    const int tx  = tid & (TILE_D - 1);
    const int ty  = tid >> 7;                    // 0 or 1
    const int col = col0 + tx;
    const int row0 = blockIdx.y * ROWS_PB + ty;

    const size_t base = (size_t)row0 * NDIMS + col;
    const float* __restrict__ pin = inputs + base;
    float* __restrict__ po = out_base + base;
    float* __restrict__ pl = out_base + (size_t)NROWS * NDIMS + base;

    const float* kb = &sm[tx];                   // knot base for this dim

    #pragma unroll 1
    for (int ii = 0; ii < 8; ii++) {
        #pragma unroll
        for (int j = 0; j < 8; j++) {
            const int ro = j * 2 * NDIMS;        // immediate offset
            const float g = pin[ro];

            const float x = fminf(fmaxf(g, -TAIL), TAIL);
            const bool inside = (g >= -TAIL) && (g <= TAIL);

            // branchless binary search over interior knots kn[0..6]
            int idx = 0;
            if (x >= kb[3 * TILE_D]) idx = 4;
            if (x >= kb[(idx + 1) * TILE_D]) idx += 2;
            if (x >= kb[idx * TILE_D]) idx += 1;

            const float* fb = &sm[OF_F + idx * TILE_D + tx];
            const float invw  = fb[0 * F_STRIDE];
            const float c     = fb[1 * F_STRIDE];
            const float delta = fb[2 * F_STRIDE];
            const float ich   = fb[3 * F_STRIDE];
            const float ih    = fb[4 * F_STRIDE];
            const float dlo   = fb[5 * F_STRIDE];
            const float s     = fb[6 * F_STRIDE];

            const float th  = fmaf(x, invw, c);      // theta
            const float th2 = th * th;
            const float t1m = th - th2;              // theta*(1-theta)

            const float den  = fmaf(s, t1m, delta);
            const float rden = __fdividef(1.0f, den);

            const float nm = fmaf(delta, th2, dlo * t1m);
            const float o  = fmaf(ih * nm, rden, ich);

            const float dmd  = delta - dlo;
            const float dn   = fmaf(fmaf(s, th, dmd + dmd), th, dlo);
            const float dd   = delta * rden;
            const float l    = __logf(dn * (dd * dd));

            po[ro] = inside ? o : g;
            pl[ro] = inside ? l : 0.0f;
        }
        pin += 16 * NDIMS;
        po  += 16 * NDIMS;
        pl  += 16 * NDIMS;
    }
}

extern "C" void kernel_launch(void* const* d_in, const int* in_sizes, int n_in,
                              void* d_out, int out_size)
{
    const float* inputs = (const float*)d_in[0];
    const float* params = (const float*)d_in[1];
    float* out = (float*)d_out;

    dim3 grid(NDIMS / TILE_D, NROWS / ROWS_PB);   // (16, 64)
    rqs_kernel<<<grid, THREADS>>>(inputs, params, out);
}

// round 6
// speedup vs baseline: 1.1224x; 1.0383x over previous
#include <cuda_runtime.h>
#include <math.h>

#define K_BINS   8
#define TAIL     3.0f
#define MIN_W    0.001f
#define MIN_H    0.001f
#define MIN_D    0.001f

#define NROWS    8192
#define NDIMS    2048
#define NPAR     (K_BINS * 3 - 1)   // 23

#define TILE_D   128
#define THREADS  256
#define ROWS_PB  128                 // rows per block

__global__ __launch_bounds__(THREADS, 5)
void rqs_kernel(const float* __restrict__ inputs,
                const float* __restrict__ params,
                float* __restrict__ out_base)
{
    // field tables: sm_f[0][bin][col] = {invw, c, delta, ich}
    //               sm_f[1][bin][col] = {ih, dlo, s, g2}
    // lane address = idx*2048 + 16*lane  ->  bank group 4*lane mod 32: conflict-free
    __shared__ float4 sm_f[2][K_BINS][TILE_D];     // 32 KB
    __shared__ float  sm_kn[7][TILE_D];            // 3.5 KB

    const int tid  = threadIdx.x;
    const int col0 = blockIdx.x * TILE_D;

    // ---------------- table build: one thread per dim ----------------
    if (tid < TILE_D) {
        const float* p = params + (size_t)(col0 + tid) * NPAR;
        float uw[K_BINS], uh[K_BINS], ud[K_BINS - 1];
        #pragma unroll
        for (int j = 0; j < K_BINS; j++)      uw[j] = p[j];
        #pragma unroll
        for (int j = 0; j < K_BINS; j++)      uh[j] = p[K_BINS + j];
        #pragma unroll
        for (int j = 0; j < K_BINS - 1; j++)  ud[j] = p[2 * K_BINS + j];

        float cw[K_BINS + 1], ch[K_BINS + 1];
        {
            float m = uw[0];
            #pragma unroll
            for (int j = 1; j < K_BINS; j++) m = fmaxf(m, uw[j]);
            float e[K_BINS], ssum = 0.0f;
            #pragma unroll
            for (int j = 0; j < K_BINS; j++) { e[j] = expf(uw[j] - m); ssum += e[j]; }
            float inv_s = 1.0f / ssum;
            float acc = 0.0f;
            cw[0] = -TAIL;
            #pragma unroll
            for (int j = 0; j < K_BINS; j++) {
                float wj = fmaf(1.0f - MIN_W * K_BINS, e[j] * inv_s, MIN_W);
                acc += wj;
                cw[j + 1] = fmaf(2.0f * TAIL, acc, -TAIL);
            }
            cw[K_BINS] = TAIL;
        }
        {
            float m = uh[0];
            #pragma unroll
            for (int j = 1; j < K_BINS; j++) m = fmaxf(m, uh[j]);
            float e[K_BINS], ssum = 0.0f;
            #pragma unroll
            for (int j = 0; j < K_BINS; j++) { e[j] = expf(uh[j] - m); ssum += e[j]; }
            float inv_s = 1.0f / ssum;
            float acc = 0.0f;
            ch[0] = -TAIL;
            #pragma unroll
            for (int j = 0; j < K_BINS; j++) {
                float hj = fmaf(1.0f - MIN_H * K_BINS, e[j] * inv_s, MIN_H);
                acc += hj;
                ch[j + 1] = fmaf(2.0f * TAIL, acc, -TAIL);
            }
            ch[K_BINS] = TAIL;
        }
        float dv[K_BINS + 1];
        dv[0] = 1.0f;                  // MIN_D + softplus(log(exp(1-MIN_D)-1)) == 1
        dv[K_BINS] = 1.0f;
        #pragma unroll
        for (int j = 0; j < K_BINS - 1; j++)
            dv[j + 1] = MIN_D + log1pf(expf(ud[j]));

        #pragma unroll
        for (int j = 0; j < 7; j++) sm_kn[j][tid] = cw[j + 1];

        #pragma unroll
        for (int b = 0; b < K_BINS; b++) {
            const float iw    = cw[b + 1] - cw[b];
            const float ih    = ch[b + 1] - ch[b];
            const float invw  = 1.0f / iw;
            const float delta = ih * invw;
            const float dlo   = dv[b];
            const float s     = dlo + dv[b + 1] - 2.0f * delta;
            const float g2    = 2.0f * (delta - dlo);
            sm_f[0][b][tid] = make_float4(invw, -cw[b] * invw, delta, ch[b]);
            sm_f[1][b][tid] = make_float4(ih, dlo, s, g2);
        }
    }
    __syncthreads();

    // ---------------- main elementwise loop ----------------
    const int tx  = tid & (TILE_D - 1);
    const int ty  = tid >> 7;                    // 0 or 1
    const int col = col0 + tx;
    const int row0 = blockIdx.y * ROWS_PB + ty;

    // knots -> registers (fixed for this thread's column)
    const float k0 = sm_kn[0][tx], k1 = sm_kn[1][tx], k2 = sm_kn[2][tx];
    const float k3 = sm_kn[3][tx], k4 = sm_kn[4][tx], k5 = sm_kn[5][tx];
    const float k6 = sm_kn[6][tx];

    const float4* __restrict__ fA = &sm_f[0][0][tx];   // + idx*128 float4
    const float4* __restrict__ fB = &sm_f[1][0][tx];

    const size_t base = (size_t)row0 * NDIMS + col;
    const float* __restrict__ pin = inputs + base;
    float* __restrict__ po = out_base + base;
    float* __restrict__ pl = out_base + (size_t)NROWS * NDIMS + base;

    #pragma unroll 1
    for (int ii = 0; ii < 8; ii++) {
        float gv[8];
        #pragma unroll
        for (int j = 0; j < 8; j++) gv[j] = pin[j * 2 * NDIMS];

        #pragma unroll
        for (int j = 0; j < 8; j++) {
            const float g = gv[j];

            // register select-tree binary search (no clamp needed)
            const bool p3 = g >= k3;
            const float m1 = p3 ? k5 : k1;
            const bool p2 = g >= m1;
            const float hi = p2 ? k6 : k4;
            const float lo = p2 ? k2 : k0;
            const float m2 = p3 ? hi : lo;
            const bool p1 = g >= m2;
            const int idx = (p3 ? 4 : 0) + (p2 ? 2 : 0) + (p1 ? 1 : 0);

            const float4 A = fA[idx * TILE_D];   // {invw, c, delta, ich}
            const float4 B = fB[idx * TILE_D];   // {ih, dlo, s, g2}

            const float th  = fmaf(g, A.x, A.y);     // theta
            const float th2 = th * th;
            const float t1m = th - th2;              // theta*(1-theta)

            const float den  = fmaf(B.z, t1m, A.z);
            const float rden = __fdividef(1.0f, den);

            const float nm = fmaf(A.z, th2, B.y * t1m);
            const float o  = fmaf(B.x * nm, rden, A.w);

            const float dn = fmaf(fmaf(B.z, th, B.w), th, B.y);
            const float dd = A.z * rden;
            const float l  = __logf(dn * (dd * dd));

            const bool inside = fabsf(g) <= TAIL;
            const int ro = j * 2 * NDIMS;
            po[ro] = inside ? o : g;
            pl[ro] = inside ? l : 0.0f;
        }
        pin += 16 * NDIMS;
        po  += 16 * NDIMS;
        pl  += 16 * NDIMS;
    }
}

extern "C" void kernel_launch(void* const* d_in, const int* in_sizes, int n_in,
                              void* d_out, int out_size)
{
    const float* inputs = (const float*)d_in[0];
    const float* params = (const float*)d_in[1];
    float* out = (float*)d_out;

    dim3 grid(NDIMS / TILE_D, NROWS / ROWS_PB);   // (16, 64)
    rqs_kernel<<<grid, THREADS>>>(inputs, params, out);
}

// round 7
// speedup vs baseline: 1.3346x; 1.1890x over previous
#include <cuda_runtime.h>
#include <math.h>

#define K_BINS   8
#define TAIL     3.0f
#define MIN_W    0.001f
#define MIN_H    0.001f
#define MIN_D    0.001f

#define NROWS    8192
#define NDIMS    2048
#define NPAR     (K_BINS * 3 - 1)   // 23

#define TILE_D   64
#define THREADS  128
#define ROWS_PB  64                  // rows per block (2 row-slots x 32 rows)

__global__ __launch_bounds__(THREADS, 10)
void rqs_kernel(const float* __restrict__ inputs,
                const float* __restrict__ params,
                float* __restrict__ out_base)
{
    // sm_f4[bin][col] = {invw, c, ih, ich}
    // sm_f2[bin][col] = {dlo, s}
    // conflict-free for divergent bin: row strides (1024B, 512B) are multiples of 128B
    __shared__ float4 sm_f4[K_BINS][TILE_D];   // 8 KB
    __shared__ float2 sm_f2[K_BINS][TILE_D];   // 4 KB
    __shared__ float  sm_kn[7][TILE_D];        // 1.75 KB

    const int tid  = threadIdx.x;
    const int col0 = blockIdx.x * TILE_D;

    // ---------------- table build: one thread per dim ----------------
    if (tid < TILE_D) {
        const float* p = params + (size_t)(col0 + tid) * NPAR;
        float uw[K_BINS], uh[K_BINS], ud[K_BINS - 1];
        #pragma unroll
        for (int j = 0; j < K_BINS; j++)      uw[j] = p[j];
        #pragma unroll
        for (int j = 0; j < K_BINS; j++)      uh[j] = p[K_BINS + j];
        #pragma unroll
        for (int j = 0; j < K_BINS - 1; j++)  ud[j] = p[2 * K_BINS + j];

        float cw[K_BINS + 1], ch[K_BINS + 1];
        {
            float m = uw[0];
            #pragma unroll
            for (int j = 1; j < K_BINS; j++) m = fmaxf(m, uw[j]);
            float e[K_BINS], ssum = 0.0f;
            #pragma unroll
            for (int j = 0; j < K_BINS; j++) { e[j] = expf(uw[j] - m); ssum += e[j]; }
            float inv_s = 1.0f / ssum;
            float acc = 0.0f;
            cw[0] = -TAIL;
            #pragma unroll
            for (int j = 0; j < K_BINS; j++) {
                float wj = fmaf(1.0f - MIN_W * K_BINS, e[j] * inv_s, MIN_W);
                acc += wj;
                cw[j + 1] = fmaf(2.0f * TAIL, acc, -TAIL);
            }
            cw[K_BINS] = TAIL;
        }
        {
            float m = uh[0];
            #pragma unroll
            for (int j = 1; j < K_BINS; j++) m = fmaxf(m, uh[j]);
            float e[K_BINS], ssum = 0.0f;
            #pragma unroll
            for (int j = 0; j < K_BINS; j++) { e[j] = expf(uh[j] - m); ssum += e[j]; }
            float inv_s = 1.0f / ssum;
            float acc = 0.0f;
            ch[0] = -TAIL;
            #pragma unroll
            for (int j = 0; j < K_BINS; j++) {
                float hj = fmaf(1.0f - MIN_H * K_BINS, e[j] * inv_s, MIN_H);
                acc += hj;
                ch[j + 1] = fmaf(2.0f * TAIL, acc, -TAIL);
            }
            ch[K_BINS] = TAIL;
        }
        float dv[K_BINS + 1];
        dv[0] = 1.0f;                  // MIN_D + softplus(log(exp(1-MIN_D)-1)) == 1
        dv[K_BINS] = 1.0f;
        #pragma unroll
        for (int j = 0; j < K_BINS - 1; j++)
            dv[j + 1] = MIN_D + log1pf(expf(ud[j]));

        #pragma unroll
        for (int j = 0; j < 7; j++) sm_kn[j][tid] = cw[j + 1];

        #pragma unroll
        for (int b = 0; b < K_BINS; b++) {
            const float iw    = cw[b + 1] - cw[b];
            const float ih    = ch[b + 1] - ch[b];
            const float invw  = 1.0f / iw;
            const float delta = ih * invw;
            const float dlo   = dv[b];
            const float s     = dlo + dv[b + 1] - 2.0f * delta;
            sm_f4[b][tid] = make_float4(invw, -cw[b] * invw, ih, ch[b]);
            sm_f2[b][tid] = make_float2(dlo, s);
        }
    }
    __syncthreads();

    // ---------------- main elementwise loop ----------------
    const int tx  = tid & (TILE_D - 1);
    const int ty  = tid >> 6;                    // 0 or 1
    const int col = col0 + tx;
    const int row0 = blockIdx.y * ROWS_PB + ty;

    // knots -> registers (fixed for this thread's column)
    const float k0 = sm_kn[0][tx], k1 = sm_kn[1][tx], k2 = sm_kn[2][tx];
    const float k3 = sm_kn[3][tx], k4 = sm_kn[4][tx], k5 = sm_kn[5][tx];
    const float k6 = sm_kn[6][tx];

    const float4* __restrict__ fA = &sm_f4[0][tx];   // + idx*TILE_D float4
    const float2* __restrict__ fB = &sm_f2[0][tx];   // + idx*TILE_D float2

    const size_t base = (size_t)row0 * NDIMS + col;
    const float* __restrict__ pin = inputs + base;
    float* __restrict__ po = out_base + base;
    float* __restrict__ pl = out_base + (size_t)NROWS * NDIMS + base;

    #pragma unroll 1
    for (int ii = 0; ii < 4; ii++) {
        float gv[8];
        #pragma unroll
        for (int j = 0; j < 8; j++) gv[j] = pin[j * 2 * NDIMS];

        #pragma unroll
        for (int j = 0; j < 8; j++) {
            const float g = gv[j];

            // register select-tree binary search
            const bool p3 = g >= k3;
            const float m1 = p3 ? k5 : k1;
            const bool p2 = g >= m1;
            const float hi = p2 ? k6 : k4;
            const float lo = p2 ? k2 : k0;
            const float m2 = p3 ? hi : lo;
            const bool p1 = g >= m2;
            const int idx = (p3 ? 4 : 0) + (p2 ? 2 : 0) + (p1 ? 1 : 0);

            const float4 A = fA[idx * TILE_D];   // {invw, c, ih, ich}
            const float2 B = fB[idx * TILE_D];   // {dlo, s}

            const float delta = A.z * A.x;           // ih * invw
            const float th  = fmaf(g, A.x, A.y);     // theta
            const float th2 = th * th;
            const float t1m = th - th2;              // theta*(1-theta)

            const float den  = fmaf(B.y, t1m, delta);
            const float rden = __fdividef(1.0f, den);

            const float nm = fmaf(delta, th2, B.x * t1m);
            const float o  = fmaf(A.z * nm, rden, A.w);

            const float g2 = 2.0f * delta - 2.0f * B.x;        // 2*(delta - dlo)
            const float dn = fmaf(fmaf(B.y, th, g2), th, B.x);
            const float dd = delta * rden;
            const float l  = __logf(dn * (dd * dd));

            const bool inside = fabsf(g) <= TAIL;
            const int ro = j * 2 * NDIMS;
            po[ro] = inside ? o : g;
            pl[ro] = inside ? l : 0.0f;
        }
        pin += 16 * NDIMS;
        po  += 16 * NDIMS;
        pl  += 16 * NDIMS;
    }
}

extern "C" void kernel_launch(void* const* d_in, const int* in_sizes, int n_in,
                              void* d_out, int out_size)
{
    const float* inputs = (const float*)d_in[0];
    const float* params = (const float*)d_in[1];
    float* out = (float*)d_out;

    dim3 grid(NDIMS / TILE_D, NROWS / ROWS_PB);   // (32, 128)
    rqs_kernel<<<grid, THREADS>>>(inputs, params, out);
}